// round 2
// baseline (speedup 1.0000x reference)
#include <cuda_runtime.h>

// ShiftedWindowAttention fused kernel, fp32, one CTA per 8x8 window.
// B=8, C=192, H=W=192, ws=8, ss=4, nh=6, hd=32, N=64, windows=24x24 per image.

#define BB   8
#define CCH  192
#define HH   192
#define WWD  192
#define WS_  8
#define SS_  4
#define NH_  6
#define HD_  32
#define NT   64
#define NWX  24
#define NWIN 576
#define NBLK (BB*NWIN)   // 4608

#define THREADS 256
#define QPAD 36          // row stride (floats) for Q/K/V tiles: float4 phase-conflict-free
#define SPAD 68          // row stride for scores
#define WTPAD 97         // staged-weight row stride: conflict-free reads & writes

// shared memory layout (in floats)
#define OFF_X   0
#define OFF_O   (NT*CCH)                  // 12288
#define OFF_WT  (OFF_O + NT*CCH)          // 24576
#define OFF_Q   (OFF_WT + 6208)           // 30784
#define OFF_K   (OFF_Q + NT*QPAD)         // 33088
#define OFF_V   (OFF_K + NT*QPAD)         // 35392
#define OFF_S   (OFF_V + NT*QPAD)         // 37696
#define OFF_TAB (OFF_S + NT*SPAD)         // 42048
#define OFF_REG (OFF_TAB + 1360)          // 43408
#define SMEM_FLOATS (OFF_REG + 64)        // 43472 -> 173888 bytes

__device__ __forceinline__ void gemm_chunk(const float* __restrict__ sA, int r0, int cbase,
                                           const float* __restrict__ sWt, int lane,
                                           float acc[8][3])
{
    // computes, for this warp: acc[i][j] += sum_{cc=0..63} sA[r0+i][cbase+cc] * Wt[cc][lane+32j]
#pragma unroll 2
    for (int cc = 0; cc < 64; cc += 4) {
        float4 a[8];
#pragma unroll
        for (int i = 0; i < 8; i++)
            a[i] = *(const float4*)&sA[(r0 + i) * CCH + cbase + cc];
#pragma unroll
        for (int t = 0; t < 4; t++) {
            float w0 = sWt[(cc + t) * WTPAD + lane];
            float w1 = sWt[(cc + t) * WTPAD + lane + 32];
            float w2 = sWt[(cc + t) * WTPAD + lane + 64];
#pragma unroll
            for (int i = 0; i < 8; i++) {
                float av = (t == 0) ? a[i].x : ((t == 1) ? a[i].y : ((t == 2) ? a[i].z : a[i].w));
                acc[i][0] = fmaf(av, w0, acc[i][0]);
                acc[i][1] = fmaf(av, w1, acc[i][1]);
                acc[i][2] = fmaf(av, w2, acc[i][2]);
            }
        }
    }
}

__global__ void __launch_bounds__(THREADS, 1)
swin_attn_kernel(const float* __restrict__ x,
                 const float* __restrict__ qkv_w,
                 const float* __restrict__ qkv_b,
                 const float* __restrict__ proj_w,
                 const float* __restrict__ proj_b,
                 const float* __restrict__ tab,
                 float* __restrict__ out)
{
    extern __shared__ float sm[];
    float* sX   = sm + OFF_X;     // window input (64 x 192)
    float* sO   = sm + OFF_O;     // attention output (64 x 192)
    float* sWt  = sm + OFF_WT;    // staged weight tile, transposed [cc][o]
    float* sQ   = sm + OFF_Q;     // 64 x HD (pad 36)
    float* sK   = sm + OFF_K;
    float* sV   = sm + OFF_V;
    float* sS   = sm + OFF_S;     // scores 64 x 64 (pad 68)
    float* sTab = sm + OFF_TAB;   // rel bias table 225 x 6
    int*   sReg = (int*)(sm + OFF_REG);

    const int tid  = threadIdx.x;
    const int warp = tid >> 5;
    const int lane = tid & 31;
    const int r0   = warp * 8;

    const int b_  = blockIdx.x;
    const int bb  = b_ / NWIN;
    const int win = b_ - bb * NWIN;
    const int wr  = win / NWX;
    const int wc  = win - wr * NWX;

    // ---- phase 0: bias table + region ids ----
    for (int i = tid; i < 225 * NH_; i += THREADS) sTab[i] = tab[i];
    if (tid < NT) {
        int ii = tid >> 3, jj = tid & 7;
        int hs = wr * WS_ + ii;
        int ws = wc * WS_ + jj;
        int hr = (hs < HH - WS_) ? 0 : ((hs < HH - SS_) ? 1 : 2);
        int wg = (ws < WWD - WS_) ? 0 : ((ws < WWD - SS_) ? 1 : 2);
        sReg[tid] = hr * 3 + wg;
    }

    // ---- phase 1: gather shifted window into sX ----
    const float* xb = x + (size_t)bb * CCH * HH * WWD;
    for (int e = tid; e < NT * CCH; e += THREADS) {
        int c = e >> 6;
        int r = e & 63;
        int ii = r >> 3, jj = r & 7;
        int hh = wr * WS_ + ii + SS_; if (hh >= HH)  hh -= HH;
        int ww = wc * WS_ + jj + SS_; if (ww >= WWD) ww -= WWD;
        sX[r * CCH + c] = xb[(c * HH + hh) * WWD + ww];
    }

    const float scale = 0.17677669529663687f;  // 32^-0.5

    // ---- per-head: QKV -> scores -> softmax -> S@V ----
    for (int h = 0; h < NH_; h++) {
        float acc[8][3];
#pragma unroll
        for (int i = 0; i < 8; i++) { acc[i][0] = 0.f; acc[i][1] = 0.f; acc[i][2] = 0.f; }

        for (int ck = 0; ck < 3; ck++) {
            const int cbase = ck * 64;
            __syncthreads();   // protect sWt from previous readers (& phase-0/1 data on first pass)
            for (int idx = tid; idx < 96 * 64; idx += THREADS) {
                int o   = idx >> 6;
                int cc2 = idx & 63;
                int grow = (o >> 5) * CCH + h * HD_ + (o & 31);  // q/k/v block rows
                sWt[cc2 * WTPAD + o] = qkv_w[grow * CCH + cbase + cc2];
            }
            __syncthreads();
            gemm_chunk(sX, r0, cbase, sWt, lane, acc);
        }

        float bq = qkv_b[h * HD_ + lane];
        float bk = qkv_b[CCH + h * HD_ + lane];
        float bv = qkv_b[2 * CCH + h * HD_ + lane];
#pragma unroll
        for (int i = 0; i < 8; i++) {
            sQ[(r0 + i) * QPAD + lane] = (acc[i][0] + bq) * scale;
            sK[(r0 + i) * QPAD + lane] = acc[i][1] + bk;
            sV[(r0 + i) * QPAD + lane] = acc[i][2] + bv;
        }
        __syncthreads();

        // scores: S[n][m] = q.k + bias + mask ; warp handles rows r0..r0+7, lane -> m, m+32
        float sc[8][2];
#pragma unroll
        for (int i = 0; i < 8; i++) { sc[i][0] = 0.f; sc[i][1] = 0.f; }
#pragma unroll
        for (int d = 0; d < HD_; d += 4) {
            float4 k0 = *(const float4*)&sK[lane * QPAD + d];
            float4 k1 = *(const float4*)&sK[(lane + 32) * QPAD + d];
#pragma unroll
            for (int i = 0; i < 8; i++) {
                float4 q = *(const float4*)&sQ[(r0 + i) * QPAD + d];
                sc[i][0] += q.x * k0.x + q.y * k0.y + q.z * k0.z + q.w * k0.w;
                sc[i][1] += q.x * k1.x + q.y * k1.y + q.z * k1.z + q.w * k1.w;
            }
        }
#pragma unroll
        for (int i = 0; i < 8; i++) {
            int n = r0 + i;
            int i1 = n >> 3, j1 = n & 7;
            int rn = sReg[n];
#pragma unroll
            for (int jj2 = 0; jj2 < 2; jj2++) {
                int m = lane + jj2 * 32;
                int i2 = m >> 3, j2 = m & 7;
                float bias = sTab[((i1 - i2 + 7) * 15 + (j1 - j2 + 7)) * NH_ + h];
                float msk  = (sReg[m] == rn) ? 0.f : -100.f;
                sS[n * SPAD + m] = sc[i][jj2] + bias + msk;
            }
        }
        __syncwarp();

        // softmax over m (warp-local; 4 lanes per row, 16 cols each)
        {
            int n  = r0 + (lane >> 2);
            float* row = &sS[n * SPAD + (lane & 3) * 16];
            float mx = row[0];
#pragma unroll
            for (int t = 1; t < 16; t++) mx = fmaxf(mx, row[t]);
            mx = fmaxf(mx, __shfl_xor_sync(0xffffffffu, mx, 1));
            mx = fmaxf(mx, __shfl_xor_sync(0xffffffffu, mx, 2));
            float sum = 0.f;
#pragma unroll
            for (int t = 0; t < 16; t++) { float e = __expf(row[t] - mx); row[t] = e; sum += e; }
            sum += __shfl_xor_sync(0xffffffffu, sum, 1);
            sum += __shfl_xor_sync(0xffffffffu, sum, 2);
            float inv = 1.f / sum;
#pragma unroll
            for (int t = 0; t < 16; t++) row[t] *= inv;
        }
        __syncwarp();

        // O_h = S @ V : warp rows r0..r0+7, lane -> head dim d
        float oa[8];
#pragma unroll
        for (int i = 0; i < 8; i++) oa[i] = 0.f;
#pragma unroll
        for (int m = 0; m < NT; m += 4) {
            float v0 = sV[(m + 0) * QPAD + lane];
            float v1 = sV[(m + 1) * QPAD + lane];
            float v2 = sV[(m + 2) * QPAD + lane];
            float v3 = sV[(m + 3) * QPAD + lane];
#pragma unroll
            for (int i = 0; i < 8; i++) {
                float4 s = *(const float4*)&sS[(r0 + i) * SPAD + m];
                oa[i] += s.x * v0 + s.y * v1 + s.z * v2 + s.w * v3;
            }
        }
#pragma unroll
        for (int i = 0; i < 8; i++) sO[(r0 + i) * CCH + h * HD_ + lane] = oa[i];
        // next head's first staging __syncthreads covers sQ/K/V reuse
    }

    // ---- proj: out = sO @ proj_w^T + proj_b -> sX ----
    for (int half = 0; half < 2; half++) {
        const int och = half * 96;
        float acc[8][3];
#pragma unroll
        for (int i = 0; i < 8; i++) { acc[i][0] = 0.f; acc[i][1] = 0.f; acc[i][2] = 0.f; }
        for (int ck = 0; ck < 3; ck++) {
            const int cbase = ck * 64;
            __syncthreads();
            for (int idx = tid; idx < 96 * 64; idx += THREADS) {
                int o   = idx >> 6;
                int cc2 = idx & 63;
                sWt[cc2 * WTPAD + o] = proj_w[(och + o) * CCH + cbase + cc2];
            }
            __syncthreads();
            gemm_chunk(sO, r0, cbase, sWt, lane, acc);
        }
        float pb0 = proj_b[och + lane];
        float pb1 = proj_b[och + lane + 32];
        float pb2 = proj_b[och + lane + 64];
#pragma unroll
        for (int i = 0; i < 8; i++) {
            sX[(r0 + i) * CCH + och + lane]      = acc[i][0] + pb0;
            sX[(r0 + i) * CCH + och + lane + 32] = acc[i][1] + pb1;
            sX[(r0 + i) * CCH + och + lane + 64] = acc[i][2] + pb2;
        }
    }
    __syncthreads();

    // ---- scatter with reverse shift ----
    float* ob = out + (size_t)bb * CCH * HH * WWD;
    for (int e = tid; e < NT * CCH; e += THREADS) {
        int c = e >> 6;
        int r = e & 63;
        int ii = r >> 3, jj = r & 7;
        int hh = wr * WS_ + ii + SS_; if (hh >= HH)  hh -= HH;
        int ww = wc * WS_ + jj + SS_; if (ww >= WWD) ww -= WWD;
        ob[(c * HH + hh) * WWD + ww] = sX[r * CCH + c];
    }
}

extern "C" void kernel_launch(void* const* d_in, const int* in_sizes, int n_in,
                              void* d_out, int out_size)
{
    const float* x      = (const float*)d_in[0];
    const float* qkv_w  = (const float*)d_in[1];
    const float* qkv_b  = (const float*)d_in[2];
    const float* proj_w = (const float*)d_in[3];
    const float* proj_b = (const float*)d_in[4];
    const float* tab    = (const float*)d_in[5];
    float* out = (float*)d_out;

    const int smem_bytes = SMEM_FLOATS * 4;
    cudaFuncSetAttribute(swin_attn_kernel,
                         cudaFuncAttributeMaxDynamicSharedMemorySize, smem_bytes);
    swin_attn_kernel<<<NBLK, THREADS, smem_bytes>>>(x, qkv_w, qkv_b, proj_w, proj_b, tab, out);
}

// round 4
// speedup vs baseline: 1.0982x; 1.0982x over previous
#include <cuda_runtime.h>

// ShiftedWindowAttention fused kernel, fp32, one CTA per 8x8 window.
// B=8, C=192, H=W=192, ws=8, ss=4, nh=6, hd=32, N=64, windows=24x24 per image.
// R2: 512 threads (16 warps), 4 rows/warp -> occupancy 25%, no register spills.

#define BB   8
#define CCH  192
#define HH   192
#define WWD  192
#define WS_  8
#define SS_  4
#define NH_  6
#define HD_  32
#define NT   64
#define NWX  24
#define NWIN 576
#define NBLK (BB*NWIN)   // 4608

#define THREADS 512
#define RPW 4            // rows per warp (16 warps x 4 = 64)
#define QPAD 36          // row stride (floats) for Q/K/V tiles: float4 phase-conflict-free
#define SPAD 68          // row stride for scores
#define WTPAD 97         // staged-weight row stride: conflict-free reads & writes

// shared memory layout (in floats)
#define OFF_X   0
#define OFF_O   (NT*CCH)                  // 12288
#define OFF_WT  (OFF_O + NT*CCH)          // 24576
#define OFF_Q   (OFF_WT + 6208)           // 30784
#define OFF_K   (OFF_Q + NT*QPAD)         // 33088
#define OFF_V   (OFF_K + NT*QPAD)         // 35392
#define OFF_S   (OFF_V + NT*QPAD)         // 37696
#define OFF_TAB (OFF_S + NT*SPAD)         // 42048
#define OFF_REG (OFF_TAB + 1360)          // 43408
#define SMEM_FLOATS (OFF_REG + 64)        // 43472 -> 173888 bytes

__device__ __forceinline__ void gemm_chunk(const float* __restrict__ sA, int r0, int cbase,
                                           const float* __restrict__ sWt, int lane,
                                           float acc[RPW][3])
{
    // acc[i][j] += sum_{cc=0..63} sA[r0+i][cbase+cc] * Wt[cc][lane+32j]
#pragma unroll 4
    for (int cc = 0; cc < 64; cc += 4) {
        float4 a[RPW];
#pragma unroll
        for (int i = 0; i < RPW; i++)
            a[i] = *(const float4*)&sA[(r0 + i) * CCH + cbase + cc];
#pragma unroll
        for (int t = 0; t < 4; t++) {
            float w0 = sWt[(cc + t) * WTPAD + lane];
            float w1 = sWt[(cc + t) * WTPAD + lane + 32];
            float w2 = sWt[(cc + t) * WTPAD + lane + 64];
#pragma unroll
            for (int i = 0; i < RPW; i++) {
                float av = (t == 0) ? a[i].x : ((t == 1) ? a[i].y : ((t == 2) ? a[i].z : a[i].w));
                acc[i][0] = fmaf(av, w0, acc[i][0]);
                acc[i][1] = fmaf(av, w1, acc[i][1]);
                acc[i][2] = fmaf(av, w2, acc[i][2]);
            }
        }
    }
}

__global__ void __launch_bounds__(THREADS, 1)
swin_attn_kernel(const float* __restrict__ x,
                 const float* __restrict__ qkv_w,
                 const float* __restrict__ qkv_b,
                 const float* __restrict__ proj_w,
                 const float* __restrict__ proj_b,
                 const float* __restrict__ tab,
                 float* __restrict__ out)
{
    extern __shared__ float sm[];
    float* sX   = sm + OFF_X;     // window input (64 x 192)
    float* sO   = sm + OFF_O;     // attention output (64 x 192)
    float* sWt  = sm + OFF_WT;    // staged weight tile, transposed [cc][o]
    float* sQ   = sm + OFF_Q;     // 64 x HD (pad 36)
    float* sK   = sm + OFF_K;
    float* sV   = sm + OFF_V;
    float* sS   = sm + OFF_S;     // scores 64 x 64 (pad 68)
    float* sTab = sm + OFF_TAB;   // rel bias table 225 x 6
    int*   sReg = (int*)(sm + OFF_REG);

    const int tid  = threadIdx.x;
    const int warp = tid >> 5;
    const int lane = tid & 31;
    const int r0   = warp * RPW;

    const int b_  = blockIdx.x;
    const int bb  = b_ / NWIN;
    const int win = b_ - bb * NWIN;
    const int wr  = win / NWX;
    const int wc  = win - wr * NWX;

    // ---- phase 0: bias table + region ids ----
    for (int i = tid; i < 225 * NH_; i += THREADS) sTab[i] = tab[i];
    if (tid < NT) {
        int ii = tid >> 3, jj = tid & 7;
        int hs = wr * WS_ + ii;
        int ws = wc * WS_ + jj;
        int hr = (hs < HH - WS_) ? 0 : ((hs < HH - SS_) ? 1 : 2);
        int wg = (ws < WWD - WS_) ? 0 : ((ws < WWD - SS_) ? 1 : 2);
        sReg[tid] = hr * 3 + wg;
    }

    // ---- phase 1: gather shifted window into sX ----
    const float* xb = x + (size_t)bb * CCH * HH * WWD;
    for (int e = tid; e < NT * CCH; e += THREADS) {
        int c = e >> 6;
        int r = e & 63;
        int ii = r >> 3, jj = r & 7;
        int hh = wr * WS_ + ii + SS_; if (hh >= HH)  hh -= HH;
        int ww = wc * WS_ + jj + SS_; if (ww >= WWD) ww -= WWD;
        sX[r * CCH + c] = xb[(c * HH + hh) * WWD + ww];
    }

    const float scale = 0.17677669529663687f;  // 32^-0.5

    // ---- per-head: QKV -> scores -> softmax -> S@V ----
    for (int h = 0; h < NH_; h++) {
        float acc[RPW][3];
#pragma unroll
        for (int i = 0; i < RPW; i++) { acc[i][0] = 0.f; acc[i][1] = 0.f; acc[i][2] = 0.f; }

        for (int ck = 0; ck < 3; ck++) {
            const int cbase = ck * 64;
            __syncthreads();   // protect sWt from previous readers (& phase-0/1 data on first pass)
            for (int idx = tid; idx < 96 * 64; idx += THREADS) {
                int o   = idx >> 6;
                int cc2 = idx & 63;
                int grow = (o >> 5) * CCH + h * HD_ + (o & 31);  // q/k/v block rows
                sWt[cc2 * WTPAD + o] = qkv_w[grow * CCH + cbase + cc2];
            }
            __syncthreads();
            gemm_chunk(sX, r0, cbase, sWt, lane, acc);
        }

        float bq = qkv_b[h * HD_ + lane];
        float bk = qkv_b[CCH + h * HD_ + lane];
        float bv = qkv_b[2 * CCH + h * HD_ + lane];
#pragma unroll
        for (int i = 0; i < RPW; i++) {
            sQ[(r0 + i) * QPAD + lane] = (acc[i][0] + bq) * scale;
            sK[(r0 + i) * QPAD + lane] = acc[i][1] + bk;
            sV[(r0 + i) * QPAD + lane] = acc[i][2] + bv;
        }
        __syncthreads();

        // scores: S[n][m] = q.k + bias + mask ; warp handles rows r0..r0+3, lane -> m, m+32
        float sc[RPW][2];
#pragma unroll
        for (int i = 0; i < RPW; i++) { sc[i][0] = 0.f; sc[i][1] = 0.f; }
#pragma unroll
        for (int d = 0; d < HD_; d += 4) {
            float4 k0 = *(const float4*)&sK[lane * QPAD + d];
            float4 k1 = *(const float4*)&sK[(lane + 32) * QPAD + d];
#pragma unroll
            for (int i = 0; i < RPW; i++) {
                float4 q = *(const float4*)&sQ[(r0 + i) * QPAD + d];
                sc[i][0] += q.x * k0.x + q.y * k0.y + q.z * k0.z + q.w * k0.w;
                sc[i][1] += q.x * k1.x + q.y * k1.y + q.z * k1.z + q.w * k1.w;
            }
        }
#pragma unroll
        for (int i = 0; i < RPW; i++) {
            int n = r0 + i;
            int i1 = n >> 3, j1 = n & 7;
            int rn = sReg[n];
#pragma unroll
            for (int jj2 = 0; jj2 < 2; jj2++) {
                int m = lane + jj2 * 32;
                int i2 = m >> 3, j2 = m & 7;
                float bias = sTab[((i1 - i2 + 7) * 15 + (j1 - j2 + 7)) * NH_ + h];
                float msk  = (sReg[m] == rn) ? 0.f : -100.f;
                sS[n * SPAD + m] = sc[i][jj2] + bias + msk;
            }
        }
        __syncwarp();

        // softmax over m (warp-local; 8 lanes per row, 8 cols each; 4 rows/warp)
        {
            int n  = r0 + (lane >> 3);
            float* row = &sS[n * SPAD + (lane & 7) * 8];
            float mx = row[0];
#pragma unroll
            for (int t = 1; t < 8; t++) mx = fmaxf(mx, row[t]);
            mx = fmaxf(mx, __shfl_xor_sync(0xffffffffu, mx, 1));
            mx = fmaxf(mx, __shfl_xor_sync(0xffffffffu, mx, 2));
            mx = fmaxf(mx, __shfl_xor_sync(0xffffffffu, mx, 4));
            float sum = 0.f;
#pragma unroll
            for (int t = 0; t < 8; t++) { float e = __expf(row[t] - mx); row[t] = e; sum += e; }
            sum += __shfl_xor_sync(0xffffffffu, sum, 1);
            sum += __shfl_xor_sync(0xffffffffu, sum, 2);
            sum += __shfl_xor_sync(0xffffffffu, sum, 4);
            float inv = 1.f / sum;
#pragma unroll
            for (int t = 0; t < 8; t++) row[t] *= inv;
        }
        __syncwarp();

        // O_h = S @ V : warp rows r0..r0+3, lane -> head dim d
        float oa[RPW];
#pragma unroll
        for (int i = 0; i < RPW; i++) oa[i] = 0.f;
#pragma unroll
        for (int m = 0; m < NT; m += 4) {
            float v0 = sV[(m + 0) * QPAD + lane];
            float v1 = sV[(m + 1) * QPAD + lane];
            float v2 = sV[(m + 2) * QPAD + lane];
            float v3 = sV[(m + 3) * QPAD + lane];
#pragma unroll
            for (int i = 0; i < RPW; i++) {
                float4 s = *(const float4*)&sS[(r0 + i) * SPAD + m];
                oa[i] += s.x * v0 + s.y * v1 + s.z * v2 + s.w * v3;
            }
        }
#pragma unroll
        for (int i = 0; i < RPW; i++) sO[(r0 + i) * CCH + h * HD_ + lane] = oa[i];
        // next head's first staging __syncthreads covers sQ/K/V reuse
    }

    // ---- proj: out = sO @ proj_w^T + proj_b -> sX ----
    for (int half = 0; half < 2; half++) {
        const int och = half * 96;
        float acc[RPW][3];
#pragma unroll
        for (int i = 0; i < RPW; i++) { acc[i][0] = 0.f; acc[i][1] = 0.f; acc[i][2] = 0.f; }
        for (int ck = 0; ck < 3; ck++) {
            const int cbase = ck * 64;
            __syncthreads();
            for (int idx = tid; idx < 96 * 64; idx += THREADS) {
                int o   = idx >> 6;
                int cc2 = idx & 63;
                sWt[cc2 * WTPAD + o] = proj_w[(och + o) * CCH + cbase + cc2];
            }
            __syncthreads();
            gemm_chunk(sO, r0, cbase, sWt, lane, acc);
        }
        float pb0 = proj_b[och + lane];
        float pb1 = proj_b[och + lane + 32];
        float pb2 = proj_b[och + lane + 64];
#pragma unroll
        for (int i = 0; i < RPW; i++) {
            sX[(r0 + i) * CCH + och + lane]      = acc[i][0] + pb0;
            sX[(r0 + i) * CCH + och + lane + 32] = acc[i][1] + pb1;
            sX[(r0 + i) * CCH + och + lane + 64] = acc[i][2] + pb2;
        }
    }
    __syncthreads();

    // ---- scatter with reverse shift ----
    float* ob = out + (size_t)bb * CCH * HH * WWD;
    for (int e = tid; e < NT * CCH; e += THREADS) {
        int c = e >> 6;
        int r = e & 63;
        int ii = r >> 3, jj = r & 7;
        int hh = wr * WS_ + ii + SS_; if (hh >= HH)  hh -= HH;
        int ww = wc * WS_ + jj + SS_; if (ww >= WWD) ww -= WWD;
        ob[(c * HH + hh) * WWD + ww] = sX[r * CCH + c];
    }
}

extern "C" void kernel_launch(void* const* d_in, const int* in_sizes, int n_in,
                              void* d_out, int out_size)
{
    const float* x      = (const float*)d_in[0];
    const float* qkv_w  = (const float*)d_in[1];
    const float* qkv_b  = (const float*)d_in[2];
    const float* proj_w = (const float*)d_in[3];
    const float* proj_b = (const float*)d_in[4];
    const float* tab    = (const float*)d_in[5];
    float* out = (float*)d_out;

    const int smem_bytes = SMEM_FLOATS * 4;
    cudaFuncSetAttribute(swin_attn_kernel,
                         cudaFuncAttributeMaxDynamicSharedMemorySize, smem_bytes);
    swin_attn_kernel<<<NBLK, THREADS, smem_bytes>>>(x, qkv_w, qkv_b, proj_w, proj_b, tab, out);
}

// round 6
// speedup vs baseline: 1.0984x; 1.0002x over previous
#include <cuda_runtime.h>

// ShiftedWindowAttention fused kernel, fp32, one CTA per 8x8 window.
// B=8, C=192, H=W=192, ws=8, ss=4, nh=6, hd=32, N=64, windows=24x24 per image.
// R2: 512 threads (16 warps), 4 rows/warp -> occupancy 25%, no register spills.

#define BB   8
#define CCH  192
#define HH   192
#define WWD  192
#define WS_  8
#define SS_  4
#define NH_  6
#define HD_  32
#define NT   64
#define NWX  24
#define NWIN 576
#define NBLK (BB*NWIN)   // 4608

#define THREADS 512
#define RPW 4            // rows per warp (16 warps x 4 = 64)
#define QPAD 36          // row stride (floats) for Q/K/V tiles: float4 phase-conflict-free
#define SPAD 68          // row stride for scores
#define WTPAD 97         // staged-weight row stride: conflict-free reads & writes

// shared memory layout (in floats)
#define OFF_X   0
#define OFF_O   (NT*CCH)                  // 12288
#define OFF_WT  (OFF_O + NT*CCH)          // 24576
#define OFF_Q   (OFF_WT + 6208)           // 30784
#define OFF_K   (OFF_Q + NT*QPAD)         // 33088
#define OFF_V   (OFF_K + NT*QPAD)         // 35392
#define OFF_S   (OFF_V + NT*QPAD)         // 37696
#define OFF_TAB (OFF_S + NT*SPAD)         // 42048
#define OFF_REG (OFF_TAB + 1360)          // 43408
#define SMEM_FLOATS (OFF_REG + 64)        // 43472 -> 173888 bytes

__device__ __forceinline__ void gemm_chunk(const float* __restrict__ sA, int r0, int cbase,
                                           const float* __restrict__ sWt, int lane,
                                           float acc[RPW][3])
{
    // acc[i][j] += sum_{cc=0..63} sA[r0+i][cbase+cc] * Wt[cc][lane+32j]
#pragma unroll 4
    for (int cc = 0; cc < 64; cc += 4) {
        float4 a[RPW];
#pragma unroll
        for (int i = 0; i < RPW; i++)
            a[i] = *(const float4*)&sA[(r0 + i) * CCH + cbase + cc];
#pragma unroll
        for (int t = 0; t < 4; t++) {
            float w0 = sWt[(cc + t) * WTPAD + lane];
            float w1 = sWt[(cc + t) * WTPAD + lane + 32];
            float w2 = sWt[(cc + t) * WTPAD + lane + 64];
#pragma unroll
            for (int i = 0; i < RPW; i++) {
                float av = (t == 0) ? a[i].x : ((t == 1) ? a[i].y : ((t == 2) ? a[i].z : a[i].w));
                acc[i][0] = fmaf(av, w0, acc[i][0]);
                acc[i][1] = fmaf(av, w1, acc[i][1]);
                acc[i][2] = fmaf(av, w2, acc[i][2]);
            }
        }
    }
}

__global__ void __launch_bounds__(THREADS, 1)
swin_attn_kernel(const float* __restrict__ x,
                 const float* __restrict__ qkv_w,
                 const float* __restrict__ qkv_b,
                 const float* __restrict__ proj_w,
                 const float* __restrict__ proj_b,
                 const float* __restrict__ tab,
                 float* __restrict__ out)
{
    extern __shared__ float sm[];
    float* sX   = sm + OFF_X;     // window input (64 x 192)
    float* sO   = sm + OFF_O;     // attention output (64 x 192)
    float* sWt  = sm + OFF_WT;    // staged weight tile, transposed [cc][o]
    float* sQ   = sm + OFF_Q;     // 64 x HD (pad 36)
    float* sK   = sm + OFF_K;
    float* sV   = sm + OFF_V;
    float* sS   = sm + OFF_S;     // scores 64 x 64 (pad 68)
    float* sTab = sm + OFF_TAB;   // rel bias table 225 x 6
    int*   sReg = (int*)(sm + OFF_REG);

    const int tid  = threadIdx.x;
    const int warp = tid >> 5;
    const int lane = tid & 31;
    const int r0   = warp * RPW;

    const int b_  = blockIdx.x;
    const int bb  = b_ / NWIN;
    const int win = b_ - bb * NWIN;
    const int wr  = win / NWX;
    const int wc  = win - wr * NWX;

    // ---- phase 0: bias table + region ids ----
    for (int i = tid; i < 225 * NH_; i += THREADS) sTab[i] = tab[i];
    if (tid < NT) {
        int ii = tid >> 3, jj = tid & 7;
        int hs = wr * WS_ + ii;
        int ws = wc * WS_ + jj;
        int hr = (hs < HH - WS_) ? 0 : ((hs < HH - SS_) ? 1 : 2);
        int wg = (ws < WWD - WS_) ? 0 : ((ws < WWD - SS_) ? 1 : 2);
        sReg[tid] = hr * 3 + wg;
    }

    // ---- phase 1: gather shifted window into sX ----
    const float* xb = x + (size_t)bb * CCH * HH * WWD;
    for (int e = tid; e < NT * CCH; e += THREADS) {
        int c = e >> 6;
        int r = e & 63;
        int ii = r >> 3, jj = r & 7;
        int hh = wr * WS_ + ii + SS_; if (hh >= HH)  hh -= HH;
        int ww = wc * WS_ + jj + SS_; if (ww >= WWD) ww -= WWD;
        sX[r * CCH + c] = xb[(c * HH + hh) * WWD + ww];
    }

    const float scale = 0.17677669529663687f;  // 32^-0.5

    // ---- per-head: QKV -> scores -> softmax -> S@V ----
    for (int h = 0; h < NH_; h++) {
        float acc[RPW][3];
#pragma unroll
        for (int i = 0; i < RPW; i++) { acc[i][0] = 0.f; acc[i][1] = 0.f; acc[i][2] = 0.f; }

        for (int ck = 0; ck < 3; ck++) {
            const int cbase = ck * 64;
            __syncthreads();   // protect sWt from previous readers (& phase-0/1 data on first pass)
            for (int idx = tid; idx < 96 * 64; idx += THREADS) {
                int o   = idx >> 6;
                int cc2 = idx & 63;
                int grow = (o >> 5) * CCH + h * HD_ + (o & 31);  // q/k/v block rows
                sWt[cc2 * WTPAD + o] = qkv_w[grow * CCH + cbase + cc2];
            }
            __syncthreads();
            gemm_chunk(sX, r0, cbase, sWt, lane, acc);
        }

        float bq = qkv_b[h * HD_ + lane];
        float bk = qkv_b[CCH + h * HD_ + lane];
        float bv = qkv_b[2 * CCH + h * HD_ + lane];
#pragma unroll
        for (int i = 0; i < RPW; i++) {
            sQ[(r0 + i) * QPAD + lane] = (acc[i][0] + bq) * scale;
            sK[(r0 + i) * QPAD + lane] = acc[i][1] + bk;
            sV[(r0 + i) * QPAD + lane] = acc[i][2] + bv;
        }
        __syncthreads();

        // scores: S[n][m] = q.k + bias + mask ; warp handles rows r0..r0+3, lane -> m, m+32
        float sc[RPW][2];
#pragma unroll
        for (int i = 0; i < RPW; i++) { sc[i][0] = 0.f; sc[i][1] = 0.f; }
#pragma unroll
        for (int d = 0; d < HD_; d += 4) {
            float4 k0 = *(const float4*)&sK[lane * QPAD + d];
            float4 k1 = *(const float4*)&sK[(lane + 32) * QPAD + d];
#pragma unroll
            for (int i = 0; i < RPW; i++) {
                float4 q = *(const float4*)&sQ[(r0 + i) * QPAD + d];
                sc[i][0] += q.x * k0.x + q.y * k0.y + q.z * k0.z + q.w * k0.w;
                sc[i][1] += q.x * k1.x + q.y * k1.y + q.z * k1.z + q.w * k1.w;
            }
        }
#pragma unroll
        for (int i = 0; i < RPW; i++) {
            int n = r0 + i;
            int i1 = n >> 3, j1 = n & 7;
            int rn = sReg[n];
#pragma unroll
            for (int jj2 = 0; jj2 < 2; jj2++) {
                int m = lane + jj2 * 32;
                int i2 = m >> 3, j2 = m & 7;
                float bias = sTab[((i1 - i2 + 7) * 15 + (j1 - j2 + 7)) * NH_ + h];
                float msk  = (sReg[m] == rn) ? 0.f : -100.f;
                sS[n * SPAD + m] = sc[i][jj2] + bias + msk;
            }
        }
        __syncwarp();

        // softmax over m (warp-local; 8 lanes per row, 8 cols each; 4 rows/warp)
        {
            int n  = r0 + (lane >> 3);
            float* row = &sS[n * SPAD + (lane & 7) * 8];
            float mx = row[0];
#pragma unroll
            for (int t = 1; t < 8; t++) mx = fmaxf(mx, row[t]);
            mx = fmaxf(mx, __shfl_xor_sync(0xffffffffu, mx, 1));
            mx = fmaxf(mx, __shfl_xor_sync(0xffffffffu, mx, 2));
            mx = fmaxf(mx, __shfl_xor_sync(0xffffffffu, mx, 4));
            float sum = 0.f;
#pragma unroll
            for (int t = 0; t < 8; t++) { float e = __expf(row[t] - mx); row[t] = e; sum += e; }
            sum += __shfl_xor_sync(0xffffffffu, sum, 1);
            sum += __shfl_xor_sync(0xffffffffu, sum, 2);
            sum += __shfl_xor_sync(0xffffffffu, sum, 4);
            float inv = 1.f / sum;
#pragma unroll
            for (int t = 0; t < 8; t++) row[t] *= inv;
        }
        __syncwarp();

        // O_h = S @ V : warp rows r0..r0+3, lane -> head dim d
        float oa[RPW];
#pragma unroll
        for (int i = 0; i < RPW; i++) oa[i] = 0.f;
#pragma unroll
        for (int m = 0; m < NT; m += 4) {
            float v0 = sV[(m + 0) * QPAD + lane];
            float v1 = sV[(m + 1) * QPAD + lane];
            float v2 = sV[(m + 2) * QPAD + lane];
            float v3 = sV[(m + 3) * QPAD + lane];
#pragma unroll
            for (int i = 0; i < RPW; i++) {
                float4 s = *(const float4*)&sS[(r0 + i) * SPAD + m];
                oa[i] += s.x * v0 + s.y * v1 + s.z * v2 + s.w * v3;
            }
        }
#pragma unroll
        for (int i = 0; i < RPW; i++) sO[(r0 + i) * CCH + h * HD_ + lane] = oa[i];
        // next head's first staging __syncthreads covers sQ/K/V reuse
    }

    // ---- proj: out = sO @ proj_w^T + proj_b -> sX ----
    for (int half = 0; half < 2; half++) {
        const int och = half * 96;
        float acc[RPW][3];
#pragma unroll
        for (int i = 0; i < RPW; i++) { acc[i][0] = 0.f; acc[i][1] = 0.f; acc[i][2] = 0.f; }
        for (int ck = 0; ck < 3; ck++) {
            const int cbase = ck * 64;
            __syncthreads();
            for (int idx = tid; idx < 96 * 64; idx += THREADS) {
                int o   = idx >> 6;
                int cc2 = idx & 63;
                sWt[cc2 * WTPAD + o] = proj_w[(och + o) * CCH + cbase + cc2];
            }
            __syncthreads();
            gemm_chunk(sO, r0, cbase, sWt, lane, acc);
        }
        float pb0 = proj_b[och + lane];
        float pb1 = proj_b[och + lane + 32];
        float pb2 = proj_b[och + lane + 64];
#pragma unroll
        for (int i = 0; i < RPW; i++) {
            sX[(r0 + i) * CCH + och + lane]      = acc[i][0] + pb0;
            sX[(r0 + i) * CCH + och + lane + 32] = acc[i][1] + pb1;
            sX[(r0 + i) * CCH + och + lane + 64] = acc[i][2] + pb2;
        }
    }
    __syncthreads();

    // ---- scatter with reverse shift ----
    float* ob = out + (size_t)bb * CCH * HH * WWD;
    for (int e = tid; e < NT * CCH; e += THREADS) {
        int c = e >> 6;
        int r = e & 63;
        int ii = r >> 3, jj = r & 7;
        int hh = wr * WS_ + ii + SS_; if (hh >= HH)  hh -= HH;
        int ww = wc * WS_ + jj + SS_; if (ww >= WWD) ww -= WWD;
        ob[(c * HH + hh) * WWD + ww] = sX[r * CCH + c];
    }
}

extern "C" void kernel_launch(void* const* d_in, const int* in_sizes, int n_in,
                              void* d_out, int out_size)
{
    const float* x      = (const float*)d_in[0];
    const float* qkv_w  = (const float*)d_in[1];
    const float* qkv_b  = (const float*)d_in[2];
    const float* proj_w = (const float*)d_in[3];
    const float* proj_b = (const float*)d_in[4];
    const float* tab    = (const float*)d_in[5];
    float* out = (float*)d_out;

    const int smem_bytes = SMEM_FLOATS * 4;
    cudaFuncSetAttribute(swin_attn_kernel,
                         cudaFuncAttributeMaxDynamicSharedMemorySize, smem_bytes);
    swin_attn_kernel<<<NBLK, THREADS, smem_bytes>>>(x, qkv_w, qkv_b, proj_w, proj_b, tab, out);
}

// round 9
// speedup vs baseline: 1.7725x; 1.6137x over previous
#include <cuda_runtime.h>
#include <cuda_bf16.h>
#include <cstdint>

// ShiftedWindowAttention: mma.sync bf16-split GEMMs + SIMT attention.
// One CTA per 8x8 window. B=8, C=192, H=W=192, ws=8, ss=4, nh=6, hd=32, N=64.
// R8 fix: weight B-fragments loaded with NON-trans ldmatrix (W is n-major = col-major B).

#define THREADS 512
#define NBLK    4608
#define CCH     192
#define HH      192
#define WWD     192

#define XP 200        // bf16 pitch for X/O planes (400B rows)
#define QP 36         // fp32 pitch for Q/K/V
#define SP 68         // fp32 pitch for scores
#define PP 100        // fp32 pitch for proj staging

// smem byte offsets
#define OFF_XH   0            // 64 x 200 bf16 = 25600
#define OFF_XL   25600
#define OFF_W    51200        // weight hi (96x200 bf16 = 38400); scores alias this
#define OFF_WL   89600        // weight lo
#define OFF_OH   128000       // attention-out hi plane
#define OFF_OL   153600
#define OFF_Q    179200       // 64 x 36 f32 = 9216 ; proj staging aliases Q/K/V
#define OFF_K    188416
#define OFF_V    197632
#define OFF_TAB  206848       // 1350 f32
#define OFF_BIAS 212248       // 768 f32: qkv_b(576) | proj_b(192)
#define OFF_RID  215320       // 64 int
#define SMEM_BYTES 215584

#define LDSM_X4(r, addr) \
    asm volatile("ldmatrix.sync.aligned.m8n8.x4.shared.b16 {%0,%1,%2,%3}, [%4];" \
        : "=r"((r)[0]), "=r"((r)[1]), "=r"((r)[2]), "=r"((r)[3]) : "r"(addr))
#define LDSM_X2(r, addr) \
    asm volatile("ldmatrix.sync.aligned.m8n8.x2.shared.b16 {%0,%1}, [%2];" \
        : "=r"((r)[0]), "=r"((r)[1]) : "r"(addr))
#define MMA_BF16(d, a, b) \
    asm volatile("mma.sync.aligned.m16n8k16.row.col.f32.bf16.bf16.f32 " \
        "{%0,%1,%2,%3}, {%4,%5,%6,%7}, {%8,%9}, {%0,%1,%2,%3};" \
        : "+f"((d)[0]), "+f"((d)[1]), "+f"((d)[2]), "+f"((d)[3]) \
        : "r"((a)[0]), "r"((a)[1]), "r"((a)[2]), "r"((a)[3]), "r"((b)[0]), "r"((b)[1]))

__device__ __forceinline__ uint32_t smem_u32(const void* p) {
    uint32_t a;
    asm("{ .reg .u64 t; cvta.to.shared.u64 t, %1; cvt.u32.u64 %0, t; }" : "=r"(a) : "l"(p));
    return a;
}

// 3-tile (16x24) bf16-split GEMM slice: acc[t] += A(16x192) @ B(nt0+t)^T
__device__ __forceinline__ void gemm3(uint32_t aH, uint32_t aL, uint32_t wH, uint32_t wL,
                                      float acc[3][4])
{
#pragma unroll
    for (int ks = 0; ks < 12; ks++) {
        uint32_t ah[4], al[4];
        LDSM_X4(ah, aH + ks * 32);
        LDSM_X4(al, aL + ks * 32);
#pragma unroll
        for (int t = 0; t < 3; t++) {
            uint32_t bh[2], bl[2];
            LDSM_X2(bh, wH + t * 3200 + ks * 32);
            LDSM_X2(bl, wL + t * 3200 + ks * 32);
            MMA_BF16(acc[t], ah, bh);
            MMA_BF16(acc[t], ah, bl);
            MMA_BF16(acc[t], al, bh);
        }
    }
}

__global__ void __launch_bounds__(THREADS, 1)
swin_mma(const float* __restrict__ x, const float* __restrict__ qkv_w,
         const float* __restrict__ qkv_b, const float* __restrict__ proj_w,
         const float* __restrict__ proj_b, const float* __restrict__ tab,
         float* __restrict__ out)
{
    extern __shared__ char smb[];
    const uint32_t smu = smem_u32(smb);
    __nv_bfloat16* sXH = (__nv_bfloat16*)(smb + OFF_XH);
    __nv_bfloat16* sXL = (__nv_bfloat16*)(smb + OFF_XL);
    __nv_bfloat16* sWH = (__nv_bfloat16*)(smb + OFF_W);
    __nv_bfloat16* sWL = (__nv_bfloat16*)(smb + OFF_WL);
    __nv_bfloat16* sOH = (__nv_bfloat16*)(smb + OFF_OH);
    __nv_bfloat16* sOL = (__nv_bfloat16*)(smb + OFF_OL);
    float* sQ   = (float*)(smb + OFF_Q);
    float* sK   = (float*)(smb + OFF_K);
    float* sV   = (float*)(smb + OFF_V);
    float* sS   = (float*)(smb + OFF_W);    // aliases weight buffer (disjoint lifetime)
    float* sPrj = (float*)(smb + OFF_Q);    // aliases Q/K/V in proj phase
    float* sTab = (float*)(smb + OFF_TAB);
    float* sBias= (float*)(smb + OFF_BIAS);
    int*   sReg = (int*)(smb + OFF_RID);

    const int tid = threadIdx.x, warp = tid >> 5, lane = tid & 31;
    const int mt = warp & 3, nt0 = 3 * (warp >> 2);
    const int r0 = warp * 4;                 // attention rows (R3 layout)

    const int b_ = blockIdx.x;
    const int bb = b_ / 576, win = b_ - bb * 576;
    const int wr = win / 24, wc = win - wr * 24;

    // ldmatrix base addresses for this thread
    const uint32_t aXH = smu + OFF_XH + (mt * 16 + (lane & 15)) * 400 + ((lane >> 4) << 4);
    const uint32_t aXL = aXH + 25600;
    const uint32_t aOH = smu + OFF_OH + (mt * 16 + (lane & 15)) * 400 + ((lane >> 4) << 4);
    const uint32_t aOL = aOH + 25600;
    const uint32_t wB  = smu + OFF_W + (lane & 7) * 400 + (((lane >> 3) & 1) << 4) + nt0 * 3200;
    const uint32_t wBL = wB + 38400;

    // ---- tables / bias / region ids ----
    for (int i = tid; i < 1350; i += THREADS) sTab[i] = tab[i];
    for (int i = tid; i < 768; i += THREADS) sBias[i] = (i < 576) ? qkv_b[i] : proj_b[i - 576];
    if (tid < 64) {
        int ii = tid >> 3, jj = tid & 7;
        int hs = wr * 8 + ii, ws = wc * 8 + jj;
        sReg[tid] = (hs < 184 ? 0 : (hs < 188 ? 1 : 2)) * 3 + (ws < 184 ? 0 : (ws < 188 ? 1 : 2));
    }

    // ---- gather shifted window -> X hi/lo bf16 planes ----
    const float* xb = x + (size_t)bb * CCH * HH * WWD;
    for (int e = tid; e < 64 * CCH; e += THREADS) {
        int c = e >> 6, r = e & 63;
        int hh2 = wr * 8 + (r >> 3) + 4; if (hh2 >= HH)  hh2 -= HH;
        int ww2 = wc * 8 + (r & 7) + 4;  if (ww2 >= WWD) ww2 -= WWD;
        float v = xb[(c * HH + hh2) * WWD + ww2];
        __nv_bfloat16 hi = __float2bfloat16(v);
        sXH[r * XP + c] = hi;
        sXL[r * XP + c] = __float2bfloat16(v - __bfloat162float(hi));
    }

    const float scale = 0.17677669529663687f;

    for (int h = 0; h < 6; h++) {
        // ---- stage head-h qkv weights (96 rows x 192) as bf16 hi/lo ----
        __syncthreads();   // prior scores consumed / first-pass gather done
        for (int idx = tid; idx < 96 * 192; idx += THREADS) {
            int o = idx / 192, c = idx - o * 192;
            int grow = (o >> 5) * 192 + h * 32 + (o & 31);
            float v = qkv_w[grow * 192 + c];
            __nv_bfloat16 hi = __float2bfloat16(v);
            sWH[o * XP + c] = hi;
            sWL[o * XP + c] = __float2bfloat16(v - __bfloat162float(hi));
        }
        __syncthreads();

        // ---- QKV GEMM: warp computes 16x24 slice of D(64x96) ----
        {
            float acc[3][4] = {};
            gemm3(aXH, aXL, wB, wBL, acc);
#pragma unroll
            for (int t = 0; t < 3; t++) {
                int gc = (nt0 + t) * 8 + (lane & 3) * 2;
                int r  = mt * 16 + (lane >> 2);
                float* dst; int lc; float b0_, b1_; bool isq = false;
                if (gc < 32)      { dst = sQ; lc = gc;      b0_ = sBias[h*32+gc];        b1_ = sBias[h*32+gc+1];        isq = true; }
                else if (gc < 64) { dst = sK; lc = gc - 32; b0_ = sBias[192+h*32+lc];    b1_ = sBias[192+h*32+lc+1]; }
                else              { dst = sV; lc = gc - 64; b0_ = sBias[384+h*32+lc];    b1_ = sBias[384+h*32+lc+1]; }
                float m = isq ? scale : 1.f;
                dst[r * QP + lc]           = (acc[t][0] + b0_) * m;
                dst[r * QP + lc + 1]       = (acc[t][1] + b1_) * m;
                dst[(r + 8) * QP + lc]     = (acc[t][2] + b0_) * m;
                dst[(r + 8) * QP + lc + 1] = (acc[t][3] + b1_) * m;
            }
        }
        __syncthreads();

        // ---- scores (rows r0..r0+3, cols lane, lane+32) ----
        float sc[4][2];
#pragma unroll
        for (int i = 0; i < 4; i++) { sc[i][0] = 0.f; sc[i][1] = 0.f; }
#pragma unroll
        for (int d = 0; d < 32; d += 4) {
            float4 k0 = *(const float4*)&sK[lane * QP + d];
            float4 k1 = *(const float4*)&sK[(lane + 32) * QP + d];
#pragma unroll
            for (int i = 0; i < 4; i++) {
                float4 q = *(const float4*)&sQ[(r0 + i) * QP + d];
                sc[i][0] += q.x * k0.x + q.y * k0.y + q.z * k0.z + q.w * k0.w;
                sc[i][1] += q.x * k1.x + q.y * k1.y + q.z * k1.z + q.w * k1.w;
            }
        }
#pragma unroll
        for (int i = 0; i < 4; i++) {
            int n = r0 + i;
            int i1 = n >> 3, j1 = n & 7;
            int rn = sReg[n];
#pragma unroll
            for (int jj2 = 0; jj2 < 2; jj2++) {
                int m2 = lane + jj2 * 32;
                int i2 = m2 >> 3, j2 = m2 & 7;
                float bia = sTab[((i1 - i2 + 7) * 15 + (j1 - j2 + 7)) * 6 + h];
                float msk = (sReg[m2] == rn) ? 0.f : -100.f;
                sS[n * SP + m2] = sc[i][jj2] + bia + msk;
            }
        }
        __syncwarp();

        // ---- softmax (8 lanes per row, 8 cols each) ----
        {
            int n = r0 + (lane >> 3);
            float* row = &sS[n * SP + (lane & 7) * 8];
            float mx = row[0];
#pragma unroll
            for (int t = 1; t < 8; t++) mx = fmaxf(mx, row[t]);
            mx = fmaxf(mx, __shfl_xor_sync(0xffffffffu, mx, 1));
            mx = fmaxf(mx, __shfl_xor_sync(0xffffffffu, mx, 2));
            mx = fmaxf(mx, __shfl_xor_sync(0xffffffffu, mx, 4));
            float sum = 0.f;
#pragma unroll
            for (int t = 0; t < 8; t++) { float e = __expf(row[t] - mx); row[t] = e; sum += e; }
            sum += __shfl_xor_sync(0xffffffffu, sum, 1);
            sum += __shfl_xor_sync(0xffffffffu, sum, 2);
            sum += __shfl_xor_sync(0xffffffffu, sum, 4);
            float inv = 1.f / sum;
#pragma unroll
            for (int t = 0; t < 8; t++) row[t] *= inv;
        }
        __syncwarp();

        // ---- O_h = S @ V -> O hi/lo planes (col h*32+lane) ----
        float oa[4] = {};
#pragma unroll
        for (int m2 = 0; m2 < 64; m2 += 4) {
            float v0 = sV[(m2 + 0) * QP + lane];
            float v1 = sV[(m2 + 1) * QP + lane];
            float v2 = sV[(m2 + 2) * QP + lane];
            float v3 = sV[(m2 + 3) * QP + lane];
#pragma unroll
            for (int i = 0; i < 4; i++) {
                float4 s = *(const float4*)&sS[(r0 + i) * SP + m2];
                oa[i] += s.x * v0 + s.y * v1 + s.z * v2 + s.w * v3;
            }
        }
#pragma unroll
        for (int i = 0; i < 4; i++) {
            int rr = r0 + i, cc = h * 32 + lane;
            __nv_bfloat16 hi = __float2bfloat16(oa[i]);
            sOH[rr * XP + cc] = hi;
            sOL[rr * XP + cc] = __float2bfloat16(oa[i] - __bfloat162float(hi));
        }
    }

    // ---- proj: out = O @ proj_w^T + proj_b, two 96-col halves ----
    float* ob = out + (size_t)bb * CCH * HH * WWD;
    for (int half = 0; half < 2; half++) {
        const int och = half * 96;
        __syncthreads();   // O planes complete / sPrj consumed
        for (int idx = tid; idx < 96 * 192; idx += THREADS) {
            int o = idx / 192, c = idx - o * 192;
            float v = proj_w[(och + o) * 192 + c];
            __nv_bfloat16 hi = __float2bfloat16(v);
            sWH[o * XP + c] = hi;
            sWL[o * XP + c] = __float2bfloat16(v - __bfloat162float(hi));
        }
        __syncthreads();
        {
            float acc[3][4] = {};
            gemm3(aOH, aOL, wB, wBL, acc);
#pragma unroll
            for (int t = 0; t < 3; t++) {
                int lc = (nt0 + t) * 8 + (lane & 3) * 2;
                int r  = mt * 16 + (lane >> 2);
                sPrj[r * PP + lc]           = acc[t][0];
                sPrj[r * PP + lc + 1]       = acc[t][1];
                sPrj[(r + 8) * PP + lc]     = acc[t][2];
                sPrj[(r + 8) * PP + lc + 1] = acc[t][3];
            }
        }
        __syncthreads();
        for (int e = tid; e < 64 * 96; e += THREADS) {
            int cl = e >> 6, r = e & 63;
            int c = och + cl;
            int hh2 = wr * 8 + (r >> 3) + 4; if (hh2 >= HH)  hh2 -= HH;
            int ww2 = wc * 8 + (r & 7) + 4;  if (ww2 >= WWD) ww2 -= WWD;
            ob[(c * HH + hh2) * WWD + ww2] = sPrj[r * PP + cl] + sBias[576 + c];
        }
    }
}

extern "C" void kernel_launch(void* const* d_in, const int* in_sizes, int n_in,
                              void* d_out, int out_size)
{
    const float* x      = (const float*)d_in[0];
    const float* qkv_w  = (const float*)d_in[1];
    const float* qkv_b  = (const float*)d_in[2];
    const float* proj_w = (const float*)d_in[3];
    const float* proj_b = (const float*)d_in[4];
    const float* tab    = (const float*)d_in[5];
    float* out = (float*)d_out;

    cudaFuncSetAttribute(swin_mma, cudaFuncAttributeMaxDynamicSharedMemorySize, SMEM_BYTES);
    swin_mma<<<NBLK, THREADS, SMEM_BYTES>>>(x, qkv_w, qkv_b, proj_w, proj_b, tab, out);
}

// round 10
// speedup vs baseline: 2.2794x; 1.2860x over previous
#include <cuda_runtime.h>
#include <cuda_bf16.h>
#include <cstdint>

// ShiftedWindowAttention: mma.sync bf16-split GEMMs + SIMT attention.
// One CTA per 8x8 window. B=8, C=192, H=W=192, ws=8, ss=4, nh=6, hd=32, N=64.
// R9: weights prepacked (bf16 hi/lo) once per launch by a helper kernel;
//     per-head staging becomes a pure uint4 smem copy.

#define THREADS 512
#define NBLK    4608
#define CCH     192
#define HH      192
#define WWD     192

#define XP 200        // bf16 pitch for X/O planes (400B rows)
#define QP 36         // fp32 pitch for Q/K/V
#define SP 68         // fp32 pitch for scores
#define PP 100        // fp32 pitch for proj staging

// smem byte offsets
#define OFF_XH   0            // 64 x 200 bf16 = 25600
#define OFF_XL   25600
#define OFF_W    51200        // weight hi (96x200 bf16 = 38400); scores alias this
#define OFF_WL   89600        // weight lo
#define OFF_OH   128000       // attention-out hi plane
#define OFF_OL   153600
#define OFF_Q    179200       // 64 x 36 f32 = 9216 ; proj staging aliases Q/K/V
#define OFF_K    188416
#define OFF_V    197632
#define OFF_TAB  206848       // 1350 f32
#define OFF_BIAS 212248       // 768 f32: qkv_b(576) | proj_b(192)
#define OFF_RID  215320       // 64 int
#define SMEM_BYTES 215584

// prepacked weight planes: stages 0-5 = qkv head h, 6-7 = proj halves.
// row pitch 256 bf16 (512B) for shift-only indexing; cols 192..255 unused.
__device__ __nv_bfloat16 gWH[8][96][256];
__device__ __nv_bfloat16 gWL[8][96][256];

#define LDSM_X4(r, addr) \
    asm volatile("ldmatrix.sync.aligned.m8n8.x4.shared.b16 {%0,%1,%2,%3}, [%4];" \
        : "=r"((r)[0]), "=r"((r)[1]), "=r"((r)[2]), "=r"((r)[3]) : "r"(addr))
#define LDSM_X2(r, addr) \
    asm volatile("ldmatrix.sync.aligned.m8n8.x2.shared.b16 {%0,%1}, [%2];" \
        : "=r"((r)[0]), "=r"((r)[1]) : "r"(addr))
#define MMA_BF16(d, a, b) \
    asm volatile("mma.sync.aligned.m16n8k16.row.col.f32.bf16.bf16.f32 " \
        "{%0,%1,%2,%3}, {%4,%5,%6,%7}, {%8,%9}, {%0,%1,%2,%3};" \
        : "+f"((d)[0]), "+f"((d)[1]), "+f"((d)[2]), "+f"((d)[3]) \
        : "r"((a)[0]), "r"((a)[1]), "r"((a)[2]), "r"((a)[3]), "r"((b)[0]), "r"((b)[1]))

__device__ __forceinline__ uint32_t smem_u32(const void* p) {
    uint32_t a;
    asm("{ .reg .u64 t; cvta.to.shared.u64 t, %1; cvt.u32.u64 %0, t; }" : "=r"(a) : "l"(p));
    return a;
}

// ---- prepack kernel: fp32 weights -> bf16 hi/lo planes (runs once per launch) ----
__global__ void prepack_w(const float* __restrict__ qkv_w, const float* __restrict__ proj_w)
{
    int idx = blockIdx.x * 256 + threadIdx.x;
    if (idx >= 8 * 96 * 192) return;
    int st = idx / (96 * 192), rem = idx - st * (96 * 192);
    int o = rem / 192, c = rem - o * 192;
    float v;
    if (st < 6) {
        int grow = (o >> 5) * 192 + st * 32 + (o & 31);
        v = qkv_w[grow * 192 + c];
    } else {
        v = proj_w[((st - 6) * 96 + o) * 192 + c];
    }
    __nv_bfloat16 hi = __float2bfloat16(v);
    gWH[st][o][c] = hi;
    gWL[st][o][c] = __float2bfloat16(v - __bfloat162float(hi));
}

// 3-tile (16x24) bf16-split GEMM slice: acc[t] += A(16x192) @ B(nt0+t)^T
__device__ __forceinline__ void gemm3(uint32_t aH, uint32_t aL, uint32_t wH, uint32_t wL,
                                      float acc[3][4])
{
#pragma unroll
    for (int ks = 0; ks < 12; ks++) {
        uint32_t ah[4], al[4];
        LDSM_X4(ah, aH + ks * 32);
        LDSM_X4(al, aL + ks * 32);
#pragma unroll
        for (int t = 0; t < 3; t++) {
            uint32_t bh[2], bl[2];
            LDSM_X2(bh, wH + t * 3200 + ks * 32);
            LDSM_X2(bl, wL + t * 3200 + ks * 32);
            MMA_BF16(acc[t], ah, bh);
            MMA_BF16(acc[t], ah, bl);
            MMA_BF16(acc[t], al, bh);
        }
    }
}

// stage prepacked weight planes into smem (pure uint4 copy, 24 chunks/row)
__device__ __forceinline__ void stage_w(char* smb, int st, int tid)
{
    for (int idx = tid; idx < 4608; idx += THREADS) {
        int pl = (idx >= 2304) ? 1 : 0;
        int k  = idx - pl * 2304;
        int r  = k / 24, ch = k - r * 24;
        const uint4* src = (const uint4*)(pl ? &gWL[st][r][0] : &gWH[st][r][0]) + ch;
        uint4* dst = (uint4*)(smb + (pl ? OFF_WL : OFF_W) + r * 400) + ch;
        *dst = *src;
    }
}

__global__ void __launch_bounds__(THREADS, 1)
swin_mma(const float* __restrict__ x, const float* __restrict__ qkv_b,
         const float* __restrict__ proj_b, const float* __restrict__ tab,
         float* __restrict__ out)
{
    extern __shared__ char smb[];
    const uint32_t smu = smem_u32(smb);
    __nv_bfloat16* sXH = (__nv_bfloat16*)(smb + OFF_XH);
    __nv_bfloat16* sXL = (__nv_bfloat16*)(smb + OFF_XL);
    __nv_bfloat16* sOH = (__nv_bfloat16*)(smb + OFF_OH);
    __nv_bfloat16* sOL = (__nv_bfloat16*)(smb + OFF_OL);
    float* sQ   = (float*)(smb + OFF_Q);
    float* sK   = (float*)(smb + OFF_K);
    float* sV   = (float*)(smb + OFF_V);
    float* sS   = (float*)(smb + OFF_W);    // aliases weight buffer (disjoint lifetime)
    float* sPrj = (float*)(smb + OFF_Q);    // aliases Q/K/V in proj phase
    float* sTab = (float*)(smb + OFF_TAB);
    float* sBias= (float*)(smb + OFF_BIAS);
    int*   sReg = (int*)(smb + OFF_RID);

    const int tid = threadIdx.x, warp = tid >> 5, lane = tid & 31;
    const int mt = warp & 3, nt0 = 3 * (warp >> 2);
    const int r0 = warp * 4;

    const int b_ = blockIdx.x;
    const int bb = b_ / 576, win = b_ - bb * 576;
    const int wr = win / 24, wc = win - wr * 24;

    // ldmatrix base addresses for this thread
    const uint32_t aXH = smu + OFF_XH + (mt * 16 + (lane & 15)) * 400 + ((lane >> 4) << 4);
    const uint32_t aXL = aXH + 25600;
    const uint32_t aOH = smu + OFF_OH + (mt * 16 + (lane & 15)) * 400 + ((lane >> 4) << 4);
    const uint32_t aOL = aOH + 25600;
    const uint32_t wB  = smu + OFF_W + (lane & 7) * 400 + (((lane >> 3) & 1) << 4) + nt0 * 3200;
    const uint32_t wBL = wB + 38400;

    // ---- tables / bias / region ids ----
    for (int i = tid; i < 1350; i += THREADS) sTab[i] = tab[i];
    for (int i = tid; i < 768; i += THREADS) sBias[i] = (i < 576) ? qkv_b[i] : proj_b[i - 576];
    if (tid < 64) {
        int ii = tid >> 3, jj = tid & 7;
        int hs = wr * 8 + ii, ws = wc * 8 + jj;
        sReg[tid] = (hs < 184 ? 0 : (hs < 188 ? 1 : 2)) * 3 + (ws < 184 ? 0 : (ws < 188 ? 1 : 2));
    }

    // ---- gather shifted window -> X hi/lo bf16 planes ----
    const float* xb = x + (size_t)bb * CCH * HH * WWD;
    for (int e = tid; e < 64 * CCH; e += THREADS) {
        int c = e >> 6, r = e & 63;
        int hh2 = wr * 8 + (r >> 3) + 4; if (hh2 >= HH)  hh2 -= HH;
        int ww2 = wc * 8 + (r & 7) + 4;  if (ww2 >= WWD) ww2 -= WWD;
        float v = xb[(c * HH + hh2) * WWD + ww2];
        __nv_bfloat16 hi = __float2bfloat16(v);
        sXH[r * XP + c] = hi;
        sXL[r * XP + c] = __float2bfloat16(v - __bfloat162float(hi));
    }

    const float scale = 0.17677669529663687f;

    for (int h = 0; h < 6; h++) {
        // ---- stage head-h prepacked weights (uint4 copy) ----
        __syncthreads();   // prior scores consumed / first-pass gather done
        stage_w(smb, h, tid);
        __syncthreads();

        // ---- QKV GEMM: warp computes 16x24 slice of D(64x96) ----
        {
            float acc[3][4] = {};
            gemm3(aXH, aXL, wB, wBL, acc);
#pragma unroll
            for (int t = 0; t < 3; t++) {
                int gc = (nt0 + t) * 8 + (lane & 3) * 2;
                int r  = mt * 16 + (lane >> 2);
                float* dst; int lc; float b0_, b1_; bool isq = false;
                if (gc < 32)      { dst = sQ; lc = gc;      b0_ = sBias[h*32+gc];        b1_ = sBias[h*32+gc+1];        isq = true; }
                else if (gc < 64) { dst = sK; lc = gc - 32; b0_ = sBias[192+h*32+lc];    b1_ = sBias[192+h*32+lc+1]; }
                else              { dst = sV; lc = gc - 64; b0_ = sBias[384+h*32+lc];    b1_ = sBias[384+h*32+lc+1]; }
                float m = isq ? scale : 1.f;
                dst[r * QP + lc]           = (acc[t][0] + b0_) * m;
                dst[r * QP + lc + 1]       = (acc[t][1] + b1_) * m;
                dst[(r + 8) * QP + lc]     = (acc[t][2] + b0_) * m;
                dst[(r + 8) * QP + lc + 1] = (acc[t][3] + b1_) * m;
            }
        }
        __syncthreads();

        // ---- scores (rows r0..r0+3, cols lane, lane+32) ----
        float sc[4][2];
#pragma unroll
        for (int i = 0; i < 4; i++) { sc[i][0] = 0.f; sc[i][1] = 0.f; }
#pragma unroll
        for (int d = 0; d < 32; d += 4) {
            float4 k0 = *(const float4*)&sK[lane * QP + d];
            float4 k1 = *(const float4*)&sK[(lane + 32) * QP + d];
#pragma unroll
            for (int i = 0; i < 4; i++) {
                float4 q = *(const float4*)&sQ[(r0 + i) * QP + d];
                sc[i][0] += q.x * k0.x + q.y * k0.y + q.z * k0.z + q.w * k0.w;
                sc[i][1] += q.x * k1.x + q.y * k1.y + q.z * k1.z + q.w * k1.w;
            }
        }
#pragma unroll
        for (int i = 0; i < 4; i++) {
            int n = r0 + i;
            int i1 = n >> 3, j1 = n & 7;
            int rn = sReg[n];
#pragma unroll
            for (int jj2 = 0; jj2 < 2; jj2++) {
                int m2 = lane + jj2 * 32;
                int i2 = m2 >> 3, j2 = m2 & 7;
                float bia = sTab[((i1 - i2 + 7) * 15 + (j1 - j2 + 7)) * 6 + h];
                float msk = (sReg[m2] == rn) ? 0.f : -100.f;
                sS[n * SP + m2] = sc[i][jj2] + bia + msk;
            }
        }
        __syncwarp();

        // ---- softmax (8 lanes per row, 8 cols each) ----
        {
            int n = r0 + (lane >> 3);
            float* row = &sS[n * SP + (lane & 7) * 8];
            float mx = row[0];
#pragma unroll
            for (int t = 1; t < 8; t++) mx = fmaxf(mx, row[t]);
            mx = fmaxf(mx, __shfl_xor_sync(0xffffffffu, mx, 1));
            mx = fmaxf(mx, __shfl_xor_sync(0xffffffffu, mx, 2));
            mx = fmaxf(mx, __shfl_xor_sync(0xffffffffu, mx, 4));
            float sum = 0.f;
#pragma unroll
            for (int t = 0; t < 8; t++) { float e = __expf(row[t] - mx); row[t] = e; sum += e; }
            sum += __shfl_xor_sync(0xffffffffu, sum, 1);
            sum += __shfl_xor_sync(0xffffffffu, sum, 2);
            sum += __shfl_xor_sync(0xffffffffu, sum, 4);
            float inv = 1.f / sum;
#pragma unroll
            for (int t = 0; t < 8; t++) row[t] *= inv;
        }
        __syncwarp();

        // ---- O_h = S @ V -> O hi/lo planes (col h*32+lane) ----
        float oa[4] = {};
#pragma unroll
        for (int m2 = 0; m2 < 64; m2 += 4) {
            float v0 = sV[(m2 + 0) * QP + lane];
            float v1 = sV[(m2 + 1) * QP + lane];
            float v2 = sV[(m2 + 2) * QP + lane];
            float v3 = sV[(m2 + 3) * QP + lane];
#pragma unroll
            for (int i = 0; i < 4; i++) {
                float4 s = *(const float4*)&sS[(r0 + i) * SP + m2];
                oa[i] += s.x * v0 + s.y * v1 + s.z * v2 + s.w * v3;
            }
        }
#pragma unroll
        for (int i = 0; i < 4; i++) {
            int rr = r0 + i, cc = h * 32 + lane;
            __nv_bfloat16 hi = __float2bfloat16(oa[i]);
            sOH[rr * XP + cc] = hi;
            sOL[rr * XP + cc] = __float2bfloat16(oa[i] - __bfloat162float(hi));
        }
    }

    // ---- proj: out = O @ proj_w^T + proj_b, two 96-col halves ----
    float* ob = out + (size_t)bb * CCH * HH * WWD;
    for (int half = 0; half < 2; half++) {
        const int och = half * 96;
        __syncthreads();   // O planes complete / sPrj consumed
        stage_w(smb, 6 + half, tid);
        __syncthreads();
        {
            float acc[3][4] = {};
            gemm3(aOH, aOL, wB, wBL, acc);
#pragma unroll
            for (int t = 0; t < 3; t++) {
                int lc = (nt0 + t) * 8 + (lane & 3) * 2;
                int r  = mt * 16 + (lane >> 2);
                sPrj[r * PP + lc]           = acc[t][0];
                sPrj[r * PP + lc + 1]       = acc[t][1];
                sPrj[(r + 8) * PP + lc]     = acc[t][2];
                sPrj[(r + 8) * PP + lc + 1] = acc[t][3];
            }
        }
        __syncthreads();
        for (int e = tid; e < 64 * 96; e += THREADS) {
            int cl = e >> 6, r = e & 63;
            int c = och + cl;
            int hh2 = wr * 8 + (r >> 3) + 4; if (hh2 >= HH)  hh2 -= HH;
            int ww2 = wc * 8 + (r & 7) + 4;  if (ww2 >= WWD) ww2 -= WWD;
            ob[(c * HH + hh2) * WWD + ww2] = sPrj[r * PP + cl] + sBias[576 + c];
        }
    }
}

extern "C" void kernel_launch(void* const* d_in, const int* in_sizes, int n_in,
                              void* d_out, int out_size)
{
    const float* x      = (const float*)d_in[0];
    const float* qkv_w  = (const float*)d_in[1];
    const float* qkv_b  = (const float*)d_in[2];
    const float* proj_w = (const float*)d_in[3];
    const float* proj_b = (const float*)d_in[4];
    const float* tab    = (const float*)d_in[5];
    float* out = (float*)d_out;

    prepack_w<<<576, 256>>>(qkv_w, proj_w);

    cudaFuncSetAttribute(swin_mma, cudaFuncAttributeMaxDynamicSharedMemorySize, SMEM_BYTES);
    swin_mma<<<NBLK, THREADS, SMEM_BYTES>>>(x, qkv_b, proj_b, tab, out);
}